// round 1
// baseline (speedup 1.0000x reference)
#include <cuda_runtime.h>
#include <cstdint>

#define N_NODES 100000
#define N_EDGES 300000
#define HID 32

// Scratch (device globals; no allocation allowed)
__device__ float g_agg1[N_NODES * HID];  // layer1 accumulator -> h1 (pre-relu)
__device__ float g_u[N_NODES * HID];     // h1 @ A   (A = nn2_w[:,0] reshaped 32x32)
__device__ float g_v[N_NODES * HID];     // h1 @ B
__device__ float g_w[N_NODES * HID];     // h1 @ C   (C = nn2_b reshaped)
__device__ float g_agg2[N_NODES * HID];  // layer2 accumulator (init h1@root2+bias2)

__device__ __forceinline__ void red_add_v4(float* addr, float a, float b, float c, float d) {
    asm volatile("red.global.add.v4.f32 [%0], {%1,%2,%3,%4};"
                 :: "l"(addr), "f"(a), "f"(b), "f"(c), "f"(d) : "memory");
}

// ---------------------------------------------------------------------------
// K1: agg1[n][o] = x[n]@root1 + bias1
// ---------------------------------------------------------------------------
__global__ void k1_init1(const float* __restrict__ x,
                         const float* __restrict__ root1,
                         const float* __restrict__ bias1) {
    int t = blockIdx.x * blockDim.x + threadIdx.x;
    if (t >= N_NODES * HID) return;
    int n = t >> 5, o = t & 31;
    float x0 = x[n * 2 + 0], x1 = x[n * 2 + 1];
    g_agg1[t] = fmaf(x0, root1[o], fmaf(x1, root1[HID + o], bias1[o]));
}

// ---------------------------------------------------------------------------
// K2: layer-1 edge messages. 8 threads per edge, 4 channels each.
// msg[o] = x0*(nw[2o]*e0 + nw[2o+1]*e1 + nb[o]) + x1*(nw[2(32+o)]*e0 + ... )
// ---------------------------------------------------------------------------
__global__ void k2_edges1(const int* __restrict__ ei,
                          const float* __restrict__ ea,
                          const float* __restrict__ nn1_w,
                          const float* __restrict__ nn1_b,
                          const float* __restrict__ x) {
    int t = blockIdx.x * blockDim.x + threadIdx.x;
    if (t >= N_EDGES * 8) return;
    int e = t >> 3;
    int q = (t & 7) * 4;              // channel base: 0,4,...,28
    int src = ei[e];
    int dst = ei[N_EDGES + e];
    float e0 = ea[2 * e + 0], e1 = ea[2 * e + 1];
    float x0 = x[src * 2 + 0], x1 = x[src * 2 + 1];
    float m[4];
#pragma unroll
    for (int c = 0; c < 4; c++) {
        int ch = q + c;
        float w0 = fmaf(nn1_w[2 * ch + 0], e0, fmaf(nn1_w[2 * ch + 1], e1, nn1_b[ch]));
        int ch2 = HID + ch;
        float w1 = fmaf(nn1_w[2 * ch2 + 0], e0, fmaf(nn1_w[2 * ch2 + 1], e1, nn1_b[ch2]));
        m[c] = fmaf(x0, w0, x1 * w1);
    }
    red_add_v4(&g_agg2[0] /*dummy avoid*/ == nullptr ? nullptr : &g_agg1[dst * HID + q],
               m[0], m[1], m[2], m[3]);
}

// ---------------------------------------------------------------------------
// K3: per-node precompute for layer 2.
//   h1 = relu(agg1)
//   u = h1@A, v = h1@B, w = h1@C, agg2 = h1@root2 + bias2
// Block = 256 threads = 8 warps; each warp computes 4 nodes (block: 32 nodes).
// Weights staged in smem (4 x 4KB); h tile (32 nodes x 32) staged in smem.
// ---------------------------------------------------------------------------
__global__ void k3_node2(const float* __restrict__ nn2_w,
                         const float* __restrict__ nn2_b,
                         const float* __restrict__ root2,
                         const float* __restrict__ bias2) {
    __shared__ float sA[1024], sB[1024], sC[1024], sR[1024], sH[32 * HID];
    int tid = threadIdx.x;
    for (int k = tid; k < 1024; k += 256) {
        sA[k] = nn2_w[2 * k + 0];
        sB[k] = nn2_w[2 * k + 1];
        sC[k] = nn2_b[k];
        sR[k] = root2[k];
    }
    int nodeBase = blockIdx.x * 32;
    for (int k = tid; k < 32 * HID; k += 256) {
        int idx = nodeBase * HID + k;
        sH[k] = (idx < N_NODES * HID) ? fmaxf(g_agg1[idx], 0.0f) : 0.0f;
    }
    __syncthreads();

    int warp = tid >> 5, o = tid & 31;
    int nb = warp * 4;  // local node base for this warp
    float u[4] = {0, 0, 0, 0}, v[4] = {0, 0, 0, 0}, w[4] = {0, 0, 0, 0}, r[4] = {0, 0, 0, 0};
#pragma unroll
    for (int i = 0; i < HID; i++) {
        float wa = sA[i * HID + o];
        float wb = sB[i * HID + o];
        float wc = sC[i * HID + o];
        float wr = sR[i * HID + o];
#pragma unroll
        for (int j = 0; j < 4; j++) {
            float h = sH[(nb + j) * HID + i];
            u[j] = fmaf(h, wa, u[j]);
            v[j] = fmaf(h, wb, v[j]);
            w[j] = fmaf(h, wc, w[j]);
            r[j] = fmaf(h, wr, r[j]);
        }
    }
    float b2 = bias2[o];
#pragma unroll
    for (int j = 0; j < 4; j++) {
        int n = nodeBase + nb + j;
        if (n < N_NODES) {
            g_u[n * HID + o] = u[j];
            g_v[n * HID + o] = v[j];
            g_w[n * HID + o] = w[j];
            g_agg2[n * HID + o] = r[j] + b2;
        }
    }
}

// ---------------------------------------------------------------------------
// K4: layer-2 edge messages. 8 threads per edge, 4 channels (float4) each.
//   msg = ea0*u[src] + ea1*v[src] + w[src] ; red into agg2[dst]
// ---------------------------------------------------------------------------
__global__ void k4_edges2(const int* __restrict__ ei,
                          const float* __restrict__ ea) {
    int t = blockIdx.x * blockDim.x + threadIdx.x;
    if (t >= N_EDGES * 8) return;
    int e = t >> 3;
    int q = (t & 7) * 4;
    int src = ei[e];
    int dst = ei[N_EDGES + e];
    float e0 = ea[2 * e + 0], e1 = ea[2 * e + 1];
    const float4 uu = *reinterpret_cast<const float4*>(&g_u[src * HID + q]);
    const float4 vv = *reinterpret_cast<const float4*>(&g_v[src * HID + q]);
    const float4 ww = *reinterpret_cast<const float4*>(&g_w[src * HID + q]);
    float m0 = fmaf(e0, uu.x, fmaf(e1, vv.x, ww.x));
    float m1 = fmaf(e0, uu.y, fmaf(e1, vv.y, ww.y));
    float m2 = fmaf(e0, uu.z, fmaf(e1, vv.z, ww.z));
    float m3 = fmaf(e0, uu.w, fmaf(e1, vv.w, ww.w));
    red_add_v4(&g_agg2[dst * HID + q], m0, m1, m2, m3);
}

// ---------------------------------------------------------------------------
// K5: epilogue. h2 = relu(agg2); h3 = relu(h2@fc1_w.T + fc1_b);
//     out = h3@fc2_w.T + fc2_b.  Warp per node.
// ---------------------------------------------------------------------------
__global__ void k5_final(const float* __restrict__ fc1_w,
                         const float* __restrict__ fc1_b,
                         const float* __restrict__ fc2_w,
                         const float* __restrict__ fc2_b,
                         float* __restrict__ out) {
    int t = blockIdx.x * blockDim.x + threadIdx.x;
    if (t >= N_NODES * HID) return;
    int n = t >> 5, o = t & 31;
    const float* a2 = &g_agg2[n * HID];
    float acc = fc1_b[o];
#pragma unroll
    for (int i = 0; i < HID; i++) {
        float h2 = fmaxf(a2[i], 0.0f);
        acc = fmaf(h2, fc1_w[o * HID + i], acc);
    }
    float h3 = fmaxf(acc, 0.0f);
    float p = h3 * fc2_w[o];
#pragma unroll
    for (int s = 16; s > 0; s >>= 1)
        p += __shfl_xor_sync(0xFFFFFFFFu, p, s);
    if (o == 0) out[n] = p + fc2_b[0];
}

// ---------------------------------------------------------------------------
extern "C" void kernel_launch(void* const* d_in, const int* in_sizes, int n_in,
                              void* d_out, int out_size) {
    const float* x       = (const float*)d_in[0];
    const int*   ei      = (const int*)  d_in[1];
    const float* ea      = (const float*)d_in[2];
    const float* nn1_w   = (const float*)d_in[3];
    const float* nn1_b   = (const float*)d_in[4];
    const float* root1   = (const float*)d_in[5];
    const float* bias1   = (const float*)d_in[6];
    const float* nn2_w   = (const float*)d_in[7];
    const float* nn2_b   = (const float*)d_in[8];
    const float* root2   = (const float*)d_in[9];
    const float* bias2   = (const float*)d_in[10];
    const float* fc1_w   = (const float*)d_in[11];
    const float* fc1_b   = (const float*)d_in[12];
    const float* fc2_w   = (const float*)d_in[13];
    const float* fc2_b   = (const float*)d_in[14];
    float* out = (float*)d_out;

    const int tpb = 256;
    int gridNode = (N_NODES * HID + tpb - 1) / tpb;   // 12500
    int gridEdge = (N_EDGES * 8 + tpb - 1) / tpb;     // 9375
    int gridK3   = (N_NODES + 31) / 32;               // 3125

    k1_init1<<<gridNode, tpb>>>(x, root1, bias1);
    k2_edges1<<<gridEdge, tpb>>>(ei, ea, nn1_w, nn1_b, x);
    k3_node2<<<gridK3, tpb>>>(nn2_w, nn2_b, root2, bias2);
    k4_edges2<<<gridEdge, tpb>>>(ei, ea);
    k5_final<<<gridNode, tpb>>>(fc1_w, fc1_b, fc2_w, fc2_b, out);
}

// round 3
// speedup vs baseline: 3.0295x; 3.0295x over previous
#include <cuda_runtime.h>
#include <cstdint>

#define N_NODES 100000
#define N_EDGES 300000
#define HID 32

// Scratch (device globals; no allocation allowed)
__device__ float g_agg1[N_NODES * HID];  // layer1 accumulator -> h1 (pre-relu)
__device__ float g_u[N_NODES * HID];     // h1 @ A   (A = nn2_w[:,0] reshaped 32x32)
__device__ float g_v[N_NODES * HID];     // h1 @ B
__device__ float g_w[N_NODES * HID];     // h1 @ C   (C = nn2_b reshaped)
__device__ float g_agg2[N_NODES * HID];  // layer2 accumulator (init h1@root2+bias2)

__device__ __forceinline__ void red_add_v4(float* addr, float a, float b, float c, float d) {
    asm volatile("red.global.add.v4.f32 [%0], {%1,%2,%3,%4};"
                 :: "l"(addr), "f"(a), "f"(b), "f"(c), "f"(d) : "memory");
}

// ---------------------------------------------------------------------------
// K1: agg1[n][o] = x[n]@root1 + bias1
// ---------------------------------------------------------------------------
__global__ void k1_init1(const float* __restrict__ x,
                         const float* __restrict__ root1,
                         const float* __restrict__ bias1) {
    int t = blockIdx.x * blockDim.x + threadIdx.x;
    if (t >= N_NODES * HID) return;
    int n = t >> 5, o = t & 31;
    float x0 = x[n * 2 + 0], x1 = x[n * 2 + 1];
    g_agg1[t] = fmaf(x0, root1[o], fmaf(x1, root1[HID + o], bias1[o]));
}

// ---------------------------------------------------------------------------
// K2: layer-1 edge messages. 8 threads per edge, 4 channels each.
// ---------------------------------------------------------------------------
__global__ void k2_edges1(const int* __restrict__ ei,
                          const float* __restrict__ ea,
                          const float* __restrict__ nn1_w,
                          const float* __restrict__ nn1_b,
                          const float* __restrict__ x) {
    int t = blockIdx.x * blockDim.x + threadIdx.x;
    if (t >= N_EDGES * 8) return;
    int e = t >> 3;
    int q = (t & 7) * 4;              // channel base: 0,4,...,28
    int src = ei[e];
    int dst = ei[N_EDGES + e];
    float e0 = ea[2 * e + 0], e1 = ea[2 * e + 1];
    float x0 = x[src * 2 + 0], x1 = x[src * 2 + 1];
    float m[4];
#pragma unroll
    for (int c = 0; c < 4; c++) {
        int ch = q + c;
        float w0 = fmaf(nn1_w[2 * ch + 0], e0, fmaf(nn1_w[2 * ch + 1], e1, nn1_b[ch]));
        int ch2 = HID + ch;
        float w1 = fmaf(nn1_w[2 * ch2 + 0], e0, fmaf(nn1_w[2 * ch2 + 1], e1, nn1_b[ch2]));
        m[c] = fmaf(x0, w0, x1 * w1);
    }
    red_add_v4(&g_agg1[dst * HID + q], m[0], m[1], m[2], m[3]);
}

// ---------------------------------------------------------------------------
// K3: per-node precompute for layer 2.
//   h1 = relu(agg1); u = h1@A, v = h1@B, w = h1@C, agg2 = h1@root2 + bias2
// Block = 256 threads = 8 warps; each warp computes 4 nodes (block: 32 nodes).
// ---------------------------------------------------------------------------
__global__ void k3_node2(const float* __restrict__ nn2_w,
                         const float* __restrict__ nn2_b,
                         const float* __restrict__ root2,
                         const float* __restrict__ bias2) {
    __shared__ float sA[1024], sB[1024], sC[1024], sR[1024], sH[32 * HID];
    int tid = threadIdx.x;
    for (int k = tid; k < 1024; k += 256) {
        sA[k] = nn2_w[2 * k + 0];
        sB[k] = nn2_w[2 * k + 1];
        sC[k] = nn2_b[k];
        sR[k] = root2[k];
    }
    int nodeBase = blockIdx.x * 32;
    for (int k = tid; k < 32 * HID; k += 256) {
        int idx = nodeBase * HID + k;
        sH[k] = (idx < N_NODES * HID) ? fmaxf(g_agg1[idx], 0.0f) : 0.0f;
    }
    __syncthreads();

    int warp = tid >> 5, o = tid & 31;
    int nb = warp * 4;  // local node base for this warp
    float u[4] = {0, 0, 0, 0}, v[4] = {0, 0, 0, 0}, w[4] = {0, 0, 0, 0}, r[4] = {0, 0, 0, 0};
#pragma unroll
    for (int i = 0; i < HID; i++) {
        float wa = sA[i * HID + o];
        float wb = sB[i * HID + o];
        float wc = sC[i * HID + o];
        float wr = sR[i * HID + o];
#pragma unroll
        for (int j = 0; j < 4; j++) {
            float h = sH[(nb + j) * HID + i];
            u[j] = fmaf(h, wa, u[j]);
            v[j] = fmaf(h, wb, v[j]);
            w[j] = fmaf(h, wc, w[j]);
            r[j] = fmaf(h, wr, r[j]);
        }
    }
    float b2 = bias2[o];
#pragma unroll
    for (int j = 0; j < 4; j++) {
        int n = nodeBase + nb + j;
        if (n < N_NODES) {
            g_u[n * HID + o] = u[j];
            g_v[n * HID + o] = v[j];
            g_w[n * HID + o] = w[j];
            g_agg2[n * HID + o] = r[j] + b2;
        }
    }
}

// ---------------------------------------------------------------------------
// K4: layer-2 edge messages. 8 threads per edge, 4 channels (float4) each.
//   msg = ea0*u[src] + ea1*v[src] + w[src] ; red into agg2[dst]
// ---------------------------------------------------------------------------
__global__ void k4_edges2(const int* __restrict__ ei,
                          const float* __restrict__ ea) {
    int t = blockIdx.x * blockDim.x + threadIdx.x;
    if (t >= N_EDGES * 8) return;
    int e = t >> 3;
    int q = (t & 7) * 4;
    int src = ei[e];
    int dst = ei[N_EDGES + e];
    float e0 = ea[2 * e + 0], e1 = ea[2 * e + 1];
    const float4 uu = *reinterpret_cast<const float4*>(&g_u[src * HID + q]);
    const float4 vv = *reinterpret_cast<const float4*>(&g_v[src * HID + q]);
    const float4 ww = *reinterpret_cast<const float4*>(&g_w[src * HID + q]);
    float m0 = fmaf(e0, uu.x, fmaf(e1, vv.x, ww.x));
    float m1 = fmaf(e0, uu.y, fmaf(e1, vv.y, ww.y));
    float m2 = fmaf(e0, uu.z, fmaf(e1, vv.z, ww.z));
    float m3 = fmaf(e0, uu.w, fmaf(e1, vv.w, ww.w));
    red_add_v4(&g_agg2[dst * HID + q], m0, m1, m2, m3);
}

// ---------------------------------------------------------------------------
// K5: epilogue. h2 = relu(agg2); h3 = relu(h2@fc1_w.T + fc1_b);
//     out = h3@fc2_w.T + fc2_b.
// fc1_w staged TRANSPOSED in smem (sW[i*32+o] = fc1_w[o*32+i]) so the
// inner-loop read is a stride-1 conflict-free LDS instead of a 32-line LDG.
// h2 loaded coalesced (1 float/lane) and broadcast via shfl.
// Block = 256 threads = 8 warps = 8 nodes.
// ---------------------------------------------------------------------------
__global__ void k5_final(const float* __restrict__ fc1_w,
                         const float* __restrict__ fc1_b,
                         const float* __restrict__ fc2_w,
                         const float* __restrict__ fc2_b,
                         float* __restrict__ out) {
    __shared__ float sW[HID * HID];  // sW[i*32+o] = fc1_w[o*32+i]
    int tid = threadIdx.x;
    for (int k = tid; k < HID * HID; k += 256) {
        int i = k >> 5, o = k & 31;
        sW[k] = fc1_w[o * HID + i];
    }
    __syncthreads();

    int warp = tid >> 5, lane = tid & 31;
    int n = blockIdx.x * 8 + warp;
    if (n >= N_NODES) return;

    float h2 = fmaxf(g_agg2[n * HID + lane], 0.0f);  // coalesced
    float acc = fc1_b[lane];
#pragma unroll
    for (int i = 0; i < HID; i++) {
        float h = __shfl_sync(0xFFFFFFFFu, h2, i);
        acc = fmaf(h, sW[i * HID + lane], acc);
    }
    float h3 = fmaxf(acc, 0.0f);
    float p = h3 * fc2_w[lane];
#pragma unroll
    for (int s = 16; s > 0; s >>= 1)
        p += __shfl_xor_sync(0xFFFFFFFFu, p, s);
    if (lane == 0) out[n] = p + fc2_b[0];
}

// ---------------------------------------------------------------------------
extern "C" void kernel_launch(void* const* d_in, const int* in_sizes, int n_in,
                              void* d_out, int out_size) {
    const float* x       = (const float*)d_in[0];
    const int*   ei      = (const int*)  d_in[1];
    const float* ea      = (const float*)d_in[2];
    const float* nn1_w   = (const float*)d_in[3];
    const float* nn1_b   = (const float*)d_in[4];
    const float* root1   = (const float*)d_in[5];
    const float* bias1   = (const float*)d_in[6];
    const float* nn2_w   = (const float*)d_in[7];
    const float* nn2_b   = (const float*)d_in[8];
    const float* root2   = (const float*)d_in[9];
    const float* bias2   = (const float*)d_in[10];
    const float* fc1_w   = (const float*)d_in[11];
    const float* fc1_b   = (const float*)d_in[12];
    const float* fc2_w   = (const float*)d_in[13];
    const float* fc2_b   = (const float*)d_in[14];
    float* out = (float*)d_out;

    const int tpb = 256;
    int gridNode = (N_NODES * HID + tpb - 1) / tpb;   // 12500
    int gridEdge = (N_EDGES * 8 + tpb - 1) / tpb;     // 9375
    int gridK3   = (N_NODES + 31) / 32;               // 3125
    int gridK5   = (N_NODES + 7) / 8;                 // 12500

    k1_init1<<<gridNode, tpb>>>(x, root1, bias1);
    k2_edges1<<<gridEdge, tpb>>>(ei, ea, nn1_w, nn1_b, x);
    k3_node2<<<gridK3, tpb>>>(nn2_w, nn2_b, root2, bias2);
    k4_edges2<<<gridEdge, tpb>>>(ei, ea);
    k5_final<<<gridK5, tpb>>>(fc1_w, fc1_b, fc2_w, fc2_b, out);
}

// round 4
// speedup vs baseline: 3.2052x; 1.0580x over previous
#include <cuda_runtime.h>
#include <cstdint>

#define N_NODES 100000
#define N_EDGES 300000
#define HID 32

// Scratch (device globals; no allocation allowed)
__device__ float g_agg1[N_NODES * HID];   // layer1 edge-sum accumulator (memset to 0)
__device__ float g_uvw[N_NODES * 96];     // interleaved per-node rows: [u(32) | v(32) | w(32)]
__device__ float g_agg2[N_NODES * HID];   // layer2 accumulator (init h1@root2+bias2 by k3)

__device__ __forceinline__ void red_add_v4(float* addr, float a, float b, float c, float d) {
    asm volatile("red.global.add.v4.f32 [%0], {%1,%2,%3,%4};"
                 :: "l"(addr), "f"(a), "f"(b), "f"(c), "f"(d) : "memory");
}

// ---------------------------------------------------------------------------
// K2: layer-1 edge messages. 2 edges per thread (even/odd pair), 4 channels.
// Weight-table reads amortized over both edges; ei via int2, ea via float4.
// ---------------------------------------------------------------------------
__global__ void k2_edges1(const int* __restrict__ ei,
                          const float* __restrict__ ea,
                          const float* __restrict__ nn1_w,
                          const float* __restrict__ nn1_b,
                          const float* __restrict__ x) {
    int t = blockIdx.x * blockDim.x + threadIdx.x;
    if (t >= N_EDGES * 4) return;
    int e = (t >> 3) * 2;                 // even edge of the pair
    int q = (t & 7) * 4;                  // channel base 0..28
    int2   ss  = *reinterpret_cast<const int2*>(&ei[e]);
    int2   dd  = *reinterpret_cast<const int2*>(&ei[N_EDGES + e]);
    float4 eav = *reinterpret_cast<const float4*>(&ea[2 * e]);  // (e0a,e0b, e1a,e1b)
    float2 xa  = *reinterpret_cast<const float2*>(&x[ss.x * 2]);
    float2 xb  = *reinterpret_cast<const float2*>(&x[ss.y * 2]);

    float m0[4], m1[4];
#pragma unroll
    for (int c = 0; c < 4; c++) {
        int ch = q + c, ch2 = ch + HID;
        float wA0 = nn1_w[2 * ch + 0],  wA1 = nn1_w[2 * ch + 1],  bA = nn1_b[ch];
        float wB0 = nn1_w[2 * ch2 + 0], wB1 = nn1_w[2 * ch2 + 1], bB = nn1_b[ch2];
        // edge e (attrs .x,.y)
        float w0a = fmaf(wA0, eav.x, fmaf(wA1, eav.y, bA));
        float w1a = fmaf(wB0, eav.x, fmaf(wB1, eav.y, bB));
        m0[c] = fmaf(xa.x, w0a, xa.y * w1a);
        // edge e+1 (attrs .z,.w)
        float w0b = fmaf(wA0, eav.z, fmaf(wA1, eav.w, bA));
        float w1b = fmaf(wB0, eav.z, fmaf(wB1, eav.w, bB));
        m1[c] = fmaf(xb.x, w0b, xb.y * w1b);
    }
    red_add_v4(&g_agg1[dd.x * HID + q], m0[0], m0[1], m0[2], m0[3]);
    red_add_v4(&g_agg1[dd.y * HID + q], m1[0], m1[1], m1[2], m1[3]);
}

// ---------------------------------------------------------------------------
// K3: per-node precompute for layer 2 (k1 folded in).
//   h1 = relu(agg1_edges + x@root1 + bias1)
//   uvw row = [h1@A | h1@B | h1@C]; agg2 = h1@root2 + bias2
// Block = 256 threads = 8 warps; each warp computes 4 nodes (block: 32 nodes).
// ---------------------------------------------------------------------------
__global__ void k3_node2(const float* __restrict__ x,
                         const float* __restrict__ root1,
                         const float* __restrict__ bias1,
                         const float* __restrict__ nn2_w,
                         const float* __restrict__ nn2_b,
                         const float* __restrict__ root2,
                         const float* __restrict__ bias2) {
    __shared__ float sA[1024], sB[1024], sC[1024], sR[1024], sH[32 * HID];
    __shared__ float sR1[64], sB1[32];
    int tid = threadIdx.x;
    for (int k = tid; k < 1024; k += 256) {
        sA[k] = nn2_w[2 * k + 0];
        sB[k] = nn2_w[2 * k + 1];
        sC[k] = nn2_b[k];
        sR[k] = root2[k];
    }
    if (tid < 64) sR1[tid] = root1[tid];
    if (tid < 32) sB1[tid] = bias1[tid];
    __syncthreads();  // sR1/sB1 ready before sH fold below

    int nodeBase = blockIdx.x * 32;
    for (int k = tid; k < 32 * HID; k += 256) {
        int n = nodeBase + (k >> 5), o = k & 31;
        float val = 0.0f;
        if (n < N_NODES) {
            float2 xv = *reinterpret_cast<const float2*>(&x[n * 2]);
            float root = fmaf(xv.x, sR1[o], fmaf(xv.y, sR1[HID + o], sB1[o]));
            val = fmaxf(g_agg1[n * HID + o] + root, 0.0f);
        }
        sH[k] = val;
    }
    __syncthreads();

    int warp = tid >> 5, o = tid & 31;
    int nb = warp * 4;  // local node base for this warp
    float u[4] = {0, 0, 0, 0}, v[4] = {0, 0, 0, 0}, w[4] = {0, 0, 0, 0}, r[4] = {0, 0, 0, 0};
#pragma unroll
    for (int i = 0; i < HID; i++) {
        float wa = sA[i * HID + o];
        float wb = sB[i * HID + o];
        float wc = sC[i * HID + o];
        float wr = sR[i * HID + o];
#pragma unroll
        for (int j = 0; j < 4; j++) {
            float h = sH[(nb + j) * HID + i];
            u[j] = fmaf(h, wa, u[j]);
            v[j] = fmaf(h, wb, v[j]);
            w[j] = fmaf(h, wc, w[j]);
            r[j] = fmaf(h, wr, r[j]);
        }
    }
    float b2 = bias2[o];
#pragma unroll
    for (int j = 0; j < 4; j++) {
        int n = nodeBase + nb + j;
        if (n < N_NODES) {
            g_uvw[n * 96 + o]      = u[j];
            g_uvw[n * 96 + 32 + o] = v[j];
            g_uvw[n * 96 + 64 + o] = w[j];
            g_agg2[n * HID + o]    = r[j] + b2;
        }
    }
}

// ---------------------------------------------------------------------------
// K4: layer-2 edge messages. 2 edges per thread, 4 channels (float4) each.
// 6 gathers batched up front (MLP ~6); msg = ea0*u + ea1*v + w; red into agg2.
// ---------------------------------------------------------------------------
__global__ void k4_edges2(const int* __restrict__ ei,
                          const float* __restrict__ ea) {
    int t = blockIdx.x * blockDim.x + threadIdx.x;
    if (t >= N_EDGES * 4) return;
    int e = (t >> 3) * 2;
    int q = (t & 7) * 4;
    int2   ss  = *reinterpret_cast<const int2*>(&ei[e]);
    int2   dd  = *reinterpret_cast<const int2*>(&ei[N_EDGES + e]);
    float4 eav = *reinterpret_cast<const float4*>(&ea[2 * e]);

    const float* ba = g_uvw + ss.x * 96;
    const float* bb = g_uvw + ss.y * 96;
    float4 u0 = *reinterpret_cast<const float4*>(ba + q);
    float4 v0 = *reinterpret_cast<const float4*>(ba + 32 + q);
    float4 w0 = *reinterpret_cast<const float4*>(ba + 64 + q);
    float4 u1 = *reinterpret_cast<const float4*>(bb + q);
    float4 v1 = *reinterpret_cast<const float4*>(bb + 32 + q);
    float4 w1 = *reinterpret_cast<const float4*>(bb + 64 + q);

    float a0 = fmaf(eav.x, u0.x, fmaf(eav.y, v0.x, w0.x));
    float a1 = fmaf(eav.x, u0.y, fmaf(eav.y, v0.y, w0.y));
    float a2 = fmaf(eav.x, u0.z, fmaf(eav.y, v0.z, w0.z));
    float a3 = fmaf(eav.x, u0.w, fmaf(eav.y, v0.w, w0.w));
    red_add_v4(&g_agg2[dd.x * HID + q], a0, a1, a2, a3);

    float b0 = fmaf(eav.z, u1.x, fmaf(eav.w, v1.x, w1.x));
    float b1 = fmaf(eav.z, u1.y, fmaf(eav.w, v1.y, w1.y));
    float b2 = fmaf(eav.z, u1.z, fmaf(eav.w, v1.z, w1.z));
    float b3 = fmaf(eav.z, u1.w, fmaf(eav.w, v1.w, w1.w));
    red_add_v4(&g_agg2[dd.y * HID + q], b0, b1, b2, b3);
}

// ---------------------------------------------------------------------------
// K5: epilogue. h2 = relu(agg2); h3 = relu(h2@fc1_w.T + fc1_b);
//     out = h3@fc2_w.T + fc2_b.  Warp per node, fc1_w transposed in smem.
// ---------------------------------------------------------------------------
__global__ void k5_final(const float* __restrict__ fc1_w,
                         const float* __restrict__ fc1_b,
                         const float* __restrict__ fc2_w,
                         const float* __restrict__ fc2_b,
                         float* __restrict__ out) {
    __shared__ float sW[HID * HID];  // sW[i*32+o] = fc1_w[o*32+i]
    int tid = threadIdx.x;
    for (int k = tid; k < HID * HID; k += 256) {
        int i = k >> 5, o = k & 31;
        sW[k] = fc1_w[o * HID + i];
    }
    __syncthreads();

    int warp = tid >> 5, lane = tid & 31;
    int n = blockIdx.x * 8 + warp;
    if (n >= N_NODES) return;

    float h2 = fmaxf(g_agg2[n * HID + lane], 0.0f);  // coalesced
    float acc = fc1_b[lane];
#pragma unroll
    for (int i = 0; i < HID; i++) {
        float h = __shfl_sync(0xFFFFFFFFu, h2, i);
        acc = fmaf(h, sW[i * HID + lane], acc);
    }
    float h3 = fmaxf(acc, 0.0f);
    float p = h3 * fc2_w[lane];
#pragma unroll
    for (int s = 16; s > 0; s >>= 1)
        p += __shfl_xor_sync(0xFFFFFFFFu, p, s);
    if (lane == 0) out[n] = p + fc2_b[0];
}

// ---------------------------------------------------------------------------
extern "C" void kernel_launch(void* const* d_in, const int* in_sizes, int n_in,
                              void* d_out, int out_size) {
    const float* x       = (const float*)d_in[0];
    const int*   ei      = (const int*)  d_in[1];
    const float* ea      = (const float*)d_in[2];
    const float* nn1_w   = (const float*)d_in[3];
    const float* nn1_b   = (const float*)d_in[4];
    const float* root1   = (const float*)d_in[5];
    const float* bias1   = (const float*)d_in[6];
    const float* nn2_w   = (const float*)d_in[7];
    const float* nn2_b   = (const float*)d_in[8];
    const float* root2   = (const float*)d_in[9];
    const float* bias2   = (const float*)d_in[10];
    const float* fc1_w   = (const float*)d_in[11];
    const float* fc1_b   = (const float*)d_in[12];
    const float* fc2_w   = (const float*)d_in[13];
    const float* fc2_b   = (const float*)d_in[14];
    float* out = (float*)d_out;

    const int tpb = 256;
    int gridEdge = (N_EDGES * 4 + tpb - 1) / tpb;     // 4688
    int gridK3   = (N_NODES + 31) / 32;               // 3125
    int gridK5   = (N_NODES + 7) / 8;                 // 12500

    // Zero the layer-1 accumulator (graph-capturable memset node).
    void* agg1_ptr = nullptr;
    cudaGetSymbolAddress(&agg1_ptr, g_agg1);
    cudaMemsetAsync(agg1_ptr, 0, sizeof(float) * N_NODES * HID, 0);

    k2_edges1<<<gridEdge, tpb>>>(ei, ea, nn1_w, nn1_b, x);
    k3_node2<<<gridK3, tpb>>>(x, root1, bias1, nn2_w, nn2_b, root2, bias2);
    k4_edges2<<<gridEdge, tpb>>>(ei, ea);
    k5_final<<<gridK5, tpb>>>(fc1_w, fc1_b, fc2_w, fc2_b, out);
}

// round 5
// speedup vs baseline: 5.8199x; 1.8158x over previous
#include <cuda_runtime.h>
#include <cstdint>

#define N_NODES 100000
#define N_EDGES 300000
#define HID 32

// Scratch (device globals; no allocation allowed)
__device__ float g_agg1[N_NODES * HID];   // layer1 edge-sum accumulator (memset to 0)
__device__ float g_uvw[N_NODES * 96];     // interleaved per-node rows: [u(32) | v(32) | w(32)]
__device__ float g_agg2[N_NODES * HID];   // layer2 accumulator (init h1@root2+bias2 by k3)

__device__ __forceinline__ void red_add_v4(float* addr, float a, float b, float c, float d) {
    asm volatile("red.global.add.v4.f32 [%0], {%1,%2,%3,%4};"
                 :: "l"(addr), "f"(a), "f"(b), "f"(c), "f"(d) : "memory");
}

// ---------------------------------------------------------------------------
// K2: layer-1 edge messages. 2 edges per thread (even/odd pair), 4 channels.
// ---------------------------------------------------------------------------
__global__ void k2_edges1(const int* __restrict__ ei,
                          const float* __restrict__ ea,
                          const float* __restrict__ nn1_w,
                          const float* __restrict__ nn1_b,
                          const float* __restrict__ x) {
    int t = blockIdx.x * blockDim.x + threadIdx.x;
    if (t >= N_EDGES * 4) return;
    int e = (t >> 3) * 2;                 // even edge of the pair
    int q = (t & 7) * 4;                  // channel base 0..28
    int2   ss  = *reinterpret_cast<const int2*>(&ei[e]);
    int2   dd  = *reinterpret_cast<const int2*>(&ei[N_EDGES + e]);
    float4 eav = *reinterpret_cast<const float4*>(&ea[2 * e]);
    float2 xa  = *reinterpret_cast<const float2*>(&x[ss.x * 2]);
    float2 xb  = *reinterpret_cast<const float2*>(&x[ss.y * 2]);

    float m0[4], m1[4];
#pragma unroll
    for (int c = 0; c < 4; c++) {
        int ch = q + c, ch2 = ch + HID;
        float wA0 = nn1_w[2 * ch + 0],  wA1 = nn1_w[2 * ch + 1],  bA = nn1_b[ch];
        float wB0 = nn1_w[2 * ch2 + 0], wB1 = nn1_w[2 * ch2 + 1], bB = nn1_b[ch2];
        float w0a = fmaf(wA0, eav.x, fmaf(wA1, eav.y, bA));
        float w1a = fmaf(wB0, eav.x, fmaf(wB1, eav.y, bB));
        m0[c] = fmaf(xa.x, w0a, xa.y * w1a);
        float w0b = fmaf(wA0, eav.z, fmaf(wA1, eav.w, bA));
        float w1b = fmaf(wB0, eav.z, fmaf(wB1, eav.w, bB));
        m1[c] = fmaf(xb.x, w0b, xb.y * w1b);
    }
    red_add_v4(&g_agg1[dd.x * HID + q], m0[0], m0[1], m0[2], m0[3]);
    red_add_v4(&g_agg1[dd.y * HID + q], m1[0], m1[1], m1[2], m1[3]);
}

// ---------------------------------------------------------------------------
// K3: per-node precompute for layer 2 (k1 folded in).
//   h1 = relu(agg1_edges + x@root1 + bias1)
//   uvw row = [h1@A | h1@B | h1@C]; agg2 = h1@root2 + bias2
// ---------------------------------------------------------------------------
__global__ void k3_node2(const float* __restrict__ x,
                         const float* __restrict__ root1,
                         const float* __restrict__ bias1,
                         const float* __restrict__ nn2_w,
                         const float* __restrict__ nn2_b,
                         const float* __restrict__ root2,
                         const float* __restrict__ bias2) {
    __shared__ float sA[1024], sB[1024], sC[1024], sR[1024], sH[32 * HID];
    __shared__ float sR1[64], sB1[32];
    int tid = threadIdx.x;
    for (int k = tid; k < 1024; k += 256) {
        sA[k] = nn2_w[2 * k + 0];
        sB[k] = nn2_w[2 * k + 1];
        sC[k] = nn2_b[k];
        sR[k] = root2[k];
    }
    if (tid < 64) sR1[tid] = root1[tid];
    if (tid < 32) sB1[tid] = bias1[tid];
    __syncthreads();

    int nodeBase = blockIdx.x * 32;
    for (int k = tid; k < 32 * HID; k += 256) {
        int n = nodeBase + (k >> 5), o = k & 31;
        float val = 0.0f;
        if (n < N_NODES) {
            float2 xv = *reinterpret_cast<const float2*>(&x[n * 2]);
            float root = fmaf(xv.x, sR1[o], fmaf(xv.y, sR1[HID + o], sB1[o]));
            val = fmaxf(g_agg1[n * HID + o] + root, 0.0f);
        }
        sH[k] = val;
    }
    __syncthreads();

    int warp = tid >> 5, o = tid & 31;
    int nb = warp * 4;
    float u[4] = {0, 0, 0, 0}, v[4] = {0, 0, 0, 0}, w[4] = {0, 0, 0, 0}, r[4] = {0, 0, 0, 0};
#pragma unroll
    for (int i = 0; i < HID; i++) {
        float wa = sA[i * HID + o];
        float wb = sB[i * HID + o];
        float wc = sC[i * HID + o];
        float wr = sR[i * HID + o];
#pragma unroll
        for (int j = 0; j < 4; j++) {
            float h = sH[(nb + j) * HID + i];
            u[j] = fmaf(h, wa, u[j]);
            v[j] = fmaf(h, wb, v[j]);
            w[j] = fmaf(h, wc, w[j]);
            r[j] = fmaf(h, wr, r[j]);
        }
    }
    float b2 = bias2[o];
#pragma unroll
    for (int j = 0; j < 4; j++) {
        int n = nodeBase + nb + j;
        if (n < N_NODES) {
            g_uvw[n * 96 + o]      = u[j];
            g_uvw[n * 96 + 32 + o] = v[j];
            g_uvw[n * 96 + 64 + o] = w[j];
            g_agg2[n * HID + o]    = r[j] + b2;
        }
    }
}

// ---------------------------------------------------------------------------
// K4: layer-2 edge messages. 2 edges per thread, 4 channels (float4) each.
// ---------------------------------------------------------------------------
__global__ void k4_edges2(const int* __restrict__ ei,
                          const float* __restrict__ ea) {
    int t = blockIdx.x * blockDim.x + threadIdx.x;
    if (t >= N_EDGES * 4) return;
    int e = (t >> 3) * 2;
    int q = (t & 7) * 4;
    int2   ss  = *reinterpret_cast<const int2*>(&ei[e]);
    int2   dd  = *reinterpret_cast<const int2*>(&ei[N_EDGES + e]);
    float4 eav = *reinterpret_cast<const float4*>(&ea[2 * e]);

    const float* ba = g_uvw + ss.x * 96;
    const float* bb = g_uvw + ss.y * 96;
    float4 u0 = *reinterpret_cast<const float4*>(ba + q);
    float4 v0 = *reinterpret_cast<const float4*>(ba + 32 + q);
    float4 w0 = *reinterpret_cast<const float4*>(ba + 64 + q);
    float4 u1 = *reinterpret_cast<const float4*>(bb + q);
    float4 v1 = *reinterpret_cast<const float4*>(bb + 32 + q);
    float4 w1 = *reinterpret_cast<const float4*>(bb + 64 + q);

    float a0 = fmaf(eav.x, u0.x, fmaf(eav.y, v0.x, w0.x));
    float a1 = fmaf(eav.x, u0.y, fmaf(eav.y, v0.y, w0.y));
    float a2 = fmaf(eav.x, u0.z, fmaf(eav.y, v0.z, w0.z));
    float a3 = fmaf(eav.x, u0.w, fmaf(eav.y, v0.w, w0.w));
    red_add_v4(&g_agg2[dd.x * HID + q], a0, a1, a2, a3);

    float b0 = fmaf(eav.z, u1.x, fmaf(eav.w, v1.x, w1.x));
    float b1 = fmaf(eav.z, u1.y, fmaf(eav.w, v1.y, w1.y));
    float b2 = fmaf(eav.z, u1.z, fmaf(eav.w, v1.z, w1.z));
    float b3 = fmaf(eav.z, u1.w, fmaf(eav.w, v1.w, w1.w));
    red_add_v4(&g_agg2[dd.y * HID + q], b0, b1, b2, b3);
}

// ---------------------------------------------------------------------------
// K5: epilogue, thread-per-node.
//   h2 = relu(agg2); h3 = relu(h2@fc1_w.T + fc1_b); out = h3@fc2_w.T + fc2_b
// fc1_w is read row-major-broadcast -> staging is a straight coalesced copy.
// h2 staged in smem padded to 36 floats/row: conflict-free writes (stride-1
// lanes) and conflict-free per-phase LDS.128 reads (lane*36 distinct banks).
// Weights read as broadcast LDS.128 (1 wavefront each). 4-way split
// accumulators break the FMA dependency chain. fc2 fused as running sum.
// Block = 256 threads = 256 nodes.
// ---------------------------------------------------------------------------
#define K5_NODES 256
__global__ void k5_final(const float* __restrict__ fc1_w,
                         const float* __restrict__ fc1_b,
                         const float* __restrict__ fc2_w,
                         const float* __restrict__ fc2_b,
                         float* __restrict__ out) {
    __shared__ float sW[HID * HID];        // fc1_w, row-major (as-is)
    __shared__ float sb[HID];
    __shared__ float sf2[HID];
    __shared__ float sH[K5_NODES * 36];    // padded h2 rows
    int tid = threadIdx.x;
    for (int k = tid; k < HID * HID; k += 256) sW[k] = fc1_w[k];   // coalesced
    if (tid < HID) { sb[tid] = fc1_b[tid]; sf2[tid] = fc2_w[tid]; }

    int base = blockIdx.x * K5_NODES;
    for (int k = tid; k < K5_NODES * HID; k += 256) {
        int nl = k >> 5, i = k & 31;
        int n = base + nl;
        float v = 0.0f;
        if (n < N_NODES) v = fmaxf(g_agg2[n * HID + i], 0.0f);     // coalesced
        sH[nl * 36 + i] = v;                                        // conflict-free
    }
    __syncthreads();

    // Each thread: its node's 32 h-values into 8 float4 registers.
    float4 h4[8];
    const float4* hp = reinterpret_cast<const float4*>(&sH[tid * 36]);
#pragma unroll
    for (int i = 0; i < 8; i++) h4[i] = hp[i];

    const float4* w4 = reinterpret_cast<const float4*>(sW);
    float total = 0.0f;
#pragma unroll 4
    for (int o = 0; o < HID; o++) {
        float a0 = sb[o], a1 = 0.0f, a2 = 0.0f, a3 = 0.0f;
#pragma unroll
        for (int i = 0; i < 8; i++) {
            float4 w = w4[o * 8 + i];   // broadcast LDS.128
            a0 = fmaf(h4[i].x, w.x, a0);
            a1 = fmaf(h4[i].y, w.y, a1);
            a2 = fmaf(h4[i].z, w.z, a2);
            a3 = fmaf(h4[i].w, w.w, a3);
        }
        float acc = (a0 + a1) + (a2 + a3);
        total = fmaf(fmaxf(acc, 0.0f), sf2[o], total);
    }
    int n = base + tid;
    if (n < N_NODES) out[n] = total + fc2_b[0];
}

// ---------------------------------------------------------------------------
extern "C" void kernel_launch(void* const* d_in, const int* in_sizes, int n_in,
                              void* d_out, int out_size) {
    const float* x       = (const float*)d_in[0];
    const int*   ei      = (const int*)  d_in[1];
    const float* ea      = (const float*)d_in[2];
    const float* nn1_w   = (const float*)d_in[3];
    const float* nn1_b   = (const float*)d_in[4];
    const float* root1   = (const float*)d_in[5];
    const float* bias1   = (const float*)d_in[6];
    const float* nn2_w   = (const float*)d_in[7];
    const float* nn2_b   = (const float*)d_in[8];
    const float* root2   = (const float*)d_in[9];
    const float* bias2   = (const float*)d_in[10];
    const float* fc1_w   = (const float*)d_in[11];
    const float* fc1_b   = (const float*)d_in[12];
    const float* fc2_w   = (const float*)d_in[13];
    const float* fc2_b   = (const float*)d_in[14];
    float* out = (float*)d_out;

    const int tpb = 256;
    int gridEdge = (N_EDGES * 4 + tpb - 1) / tpb;         // 4688
    int gridK3   = (N_NODES + 31) / 32;                   // 3125
    int gridK5   = (N_NODES + K5_NODES - 1) / K5_NODES;   // 391

    void* agg1_ptr = nullptr;
    cudaGetSymbolAddress(&agg1_ptr, g_agg1);
    cudaMemsetAsync(agg1_ptr, 0, sizeof(float) * N_NODES * HID, 0);

    k2_edges1<<<gridEdge, tpb>>>(ei, ea, nn1_w, nn1_b, x);
    k3_node2<<<gridK3, tpb>>>(x, root1, bias1, nn2_w, nn2_b, root2, bias2);
    k4_edges2<<<gridEdge, tpb>>>(ei, ea);
    k5_final<<<gridK5, tpb>>>(fc1_w, fc1_b, fc2_w, fc2_b, out);
}